// round 1
// baseline (speedup 1.0000x reference)
#include <cuda_runtime.h>

// Problem constants (from reference: B=16, L=192, E=128, T=25)
#define BB   16
#define LL   192
#define EE   128
#define TT   25
#define NI   (LL - TT - 1)          // 166 block rows per batch
#define LOUT (TT + 1 + NI * LL)     // 31898 output rows per batch
#define E4   (EE / 4)               // 32 float4 per row
#define G    4                      // i-values per block

// Scratch: s0[b,l,e] = sigmoid(x*(W0-W1) + (b0-b1)). 16*192*128 floats = 1.5 MB (L2-resident).
__device__ float g_S[BB * LL * EE];

// Kernel 1: compute s0 table once; also copy the 26-row head x[:, :T+1, :] -> out[:, :T+1, :].
__global__ void prep_kernel(const float* __restrict__ x,
                            const float* __restrict__ W,
                            const float* __restrict__ bvec,
                            float* __restrict__ out) {
    int idx = blockIdx.x * blockDim.x + threadIdx.x;
    float dw = W[0] - W[1];
    float db = bvec[0] - bvec[1];
    if (idx < BB * LL * EE) {
        float v = x[idx];
        float z = fmaf(v, dw, db);
        // s0 = sigmoid(z)
        g_S[idx] = __frcp_rn(1.0f + __expf(-z));
    }
    if (idx < BB * (TT + 1) * EE) {
        int e = idx % EE;
        int t = (idx / EE) % (TT + 1);
        int b = idx / (EE * (TT + 1));
        out[((size_t)b * LOUT + t) * EE + e] = x[((size_t)b * LL + t) * EE + e];
    }
}

// Kernel 2: blocks[b,i,l,:] = fma(xi - xp, s0[b,l,:], xp)
// Block = (tile of G i-values, batch b). 128 threads: lsub = tid/32 (4 l's in flight),
// e4 = tid%32 (float4 lane). All loads/stores are 128-bit, fully coalesced.
__global__ void __launch_bounds__(128, 8)
blocks_kernel(const float* __restrict__ x, float* __restrict__ out) {
    const int b    = blockIdx.y;
    const int tile = blockIdx.x;
    const int tid  = threadIdx.x;
    const int lsub = tid >> 5;       // 0..3
    const int e4   = tid & 31;       // 0..31

    const float4* __restrict__ x4 = reinterpret_cast<const float4*>(x);
    const float4* __restrict__ S4 = reinterpret_cast<const float4*>(g_S);
    float4* __restrict__ o4       = reinterpret_cast<float4*>(out);

    const int ibase = tile * G;

    float4 dd[G], pp[G];
    bool valid[G];
#pragma unroll
    for (int g = 0; g < G; g++) {
        int i = ibase + g;
        valid[g] = (i < NI);
        int ii = valid[g] ? i : 0;
        float4 a = x4[((size_t)b * LL + (TT + 1 + ii)) * E4 + e4];  // xi row
        float4 p = x4[((size_t)b * LL + (ii + 1)) * E4 + e4];       // xp row
        pp[g] = p;
        dd[g].x = a.x - p.x;
        dd[g].y = a.y - p.y;
        dd[g].z = a.z - p.z;
        dd[g].w = a.w - p.w;
    }

    const float4* __restrict__ Sb = S4 + (size_t)b * LL * E4;
    const size_t outrow0 = (size_t)b * LOUT + (TT + 1);

    for (int l0 = 0; l0 < LL; l0 += 4) {
        const int l = l0 + lsub;
        float4 s = Sb[(size_t)l * E4 + e4];
#pragma unroll
        for (int g = 0; g < G; g++) {
            if (valid[g]) {
                float4 o;
                o.x = fmaf(dd[g].x, s.x, pp[g].x);
                o.y = fmaf(dd[g].y, s.y, pp[g].y);
                o.z = fmaf(dd[g].z, s.z, pp[g].z);
                o.w = fmaf(dd[g].w, s.w, pp[g].w);
                o4[(outrow0 + (size_t)(ibase + g) * LL + l) * E4 + e4] = o;
            }
        }
    }
}

extern "C" void kernel_launch(void* const* d_in, const int* in_sizes, int n_in,
                              void* d_out, int out_size) {
    const float* x  = (const float*)d_in[0];
    const float* W  = (const float*)d_in[1];
    const float* bv = (const float*)d_in[2];
    float* out = (float*)d_out;

    // Kernel 1: 393216 elements -> 1536 blocks of 256
    int n1 = BB * LL * EE;
    prep_kernel<<<(n1 + 255) / 256, 256>>>(x, W, bv, out);

    // Kernel 2: tiles of G i-values x 16 batches
    dim3 grid((NI + G - 1) / G, BB);   // (42, 16)
    blocks_kernel<<<grid, 128>>>(x, out);
}

// round 2
// speedup vs baseline: 1.0786x; 1.0786x over previous
#include <cuda_runtime.h>

// Problem constants (from reference: B=16, L=192, E=128, T=25)
#define BB   16
#define LL   192
#define EE   128
#define TT   25
#define NI   (LL - TT - 1)          // 166 block rows per batch
#define LOUT (TT + 1 + NI * LL)     // 31898 output rows per batch
#define E4   (EE / 4)               // 32 float4 per row
#define G    4                      // i-values per block
#define NZ   4                      // l-slices per (tile,b)
#define LCH  (LL / NZ)              // 48 l-values per slice

// Scratch: s0[b,l,e] = sigmoid(x*(W0-W1) + (b0-b1)). 1.5 MB (L2-resident).
__device__ float g_S[BB * LL * EE];

// Kernel 1: compute s0 table once; also copy the 26-row head x[:, :T+1, :] -> out.
__global__ void prep_kernel(const float* __restrict__ x,
                            const float* __restrict__ W,
                            const float* __restrict__ bvec,
                            float* __restrict__ out) {
    int idx = blockIdx.x * blockDim.x + threadIdx.x;
    float dw = W[0] - W[1];
    float db = bvec[0] - bvec[1];
    if (idx < BB * LL * EE) {
        float v = x[idx];
        float z = fmaf(v, dw, db);
        g_S[idx] = __frcp_rn(1.0f + __expf(-z));   // sigmoid
    }
    if (idx < BB * (TT + 1) * EE) {
        int e = idx % EE;
        int t = (idx / EE) % (TT + 1);
        int b = idx / (EE * (TT + 1));
        out[((size_t)b * LOUT + t) * EE + e] = x[((size_t)b * LL + t) * EE + e];
    }
}

// Kernel 2: blocks[b,i,l,:] = fma(xi - xp, s0[b,l,:], xp)
// Grid: (i-tiles, batch, l-slices). 128 threads: lsub = tid/32 picks one of 4
// l's per iteration, e4 = tid%32 is the float4 lane. All memory ops 128-bit,
// coalesced. Output written with streaming stores (never re-read).
__global__ void __launch_bounds__(128, 8)
blocks_kernel(const float* __restrict__ x, float* __restrict__ out) {
    const int b    = blockIdx.y;
    const int tile = blockIdx.x;
    const int zl   = blockIdx.z;
    const int tid  = threadIdx.x;
    const int lsub = tid >> 5;       // 0..3
    const int e4   = tid & 31;       // 0..31

    const float4* __restrict__ x4 = reinterpret_cast<const float4*>(x);
    const float4* __restrict__ S4 = reinterpret_cast<const float4*>(g_S);
    float4* __restrict__ o4       = reinterpret_cast<float4*>(out);

    const int ibase = tile * G;

    float4 dd[G], pp[G];
    bool valid[G];
#pragma unroll
    for (int g = 0; g < G; g++) {
        int i = ibase + g;
        valid[g] = (i < NI);
        int ii = valid[g] ? i : 0;
        float4 a = __ldg(&x4[((size_t)b * LL + (TT + 1 + ii)) * E4 + e4]);  // xi
        float4 p = __ldg(&x4[((size_t)b * LL + (ii + 1)) * E4 + e4]);       // xp
        pp[g] = p;
        dd[g].x = a.x - p.x;
        dd[g].y = a.y - p.y;
        dd[g].z = a.z - p.z;
        dd[g].w = a.w - p.w;
    }

    const float4* __restrict__ Sb = S4 + (size_t)b * LL * E4;
    const size_t outrow0 = (size_t)b * LOUT + (TT + 1);
    const int lbeg = zl * LCH;

#pragma unroll 4
    for (int l0 = 0; l0 < LCH; l0 += 4) {
        const int l = lbeg + l0 + lsub;
        float4 s = __ldg(&Sb[(size_t)l * E4 + e4]);
#pragma unroll
        for (int g = 0; g < G; g++) {
            if (valid[g]) {
                float4 o;
                o.x = fmaf(dd[g].x, s.x, pp[g].x);
                o.y = fmaf(dd[g].y, s.y, pp[g].y);
                o.z = fmaf(dd[g].z, s.z, pp[g].z);
                o.w = fmaf(dd[g].w, s.w, pp[g].w);
                __stcs(&o4[(outrow0 + (size_t)(ibase + g) * LL + l) * E4 + e4], o);
            }
        }
    }
}

extern "C" void kernel_launch(void* const* d_in, const int* in_sizes, int n_in,
                              void* d_out, int out_size) {
    const float* x  = (const float*)d_in[0];
    const float* W  = (const float*)d_in[1];
    const float* bv = (const float*)d_in[2];
    float* out = (float*)d_out;

    int n1 = BB * LL * EE;
    prep_kernel<<<(n1 + 255) / 256, 256>>>(x, W, bv, out);

    dim3 grid((NI + G - 1) / G, BB, NZ);   // (42, 16, 4) = 2688 CTAs
    blocks_kernel<<<grid, 128>>>(x, out);
}

// round 3
// speedup vs baseline: 1.1732x; 1.0877x over previous
#include <cuda_runtime.h>

// Problem constants (from reference: B=16, L=192, E=128, T=25)
#define BB   16
#define LL   192
#define EE   128
#define TT   25
#define NI   (LL - TT - 1)          // 166 block rows per batch (even!)
#define LOUT (TT + 1 + NI * LL)     // 31898 output rows per batch
#define E4   (EE / 4)               // 32 float4 per row
#define G    2                      // i-values per block (166 % 2 == 0 -> no bounds checks)
#define NZ   8                      // l-slices per (tile,b)
#define LCH  (LL / NZ)              // 24 l-values per slice

// Scratch: s0[b,l,e] = sigmoid(x*(W0-W1) + (b0-b1)). 1.5 MB (L2-resident).
__device__ float g_S[BB * LL * EE];

// Kernel 1: compute s0 table once; also copy the 26-row head x[:, :T+1, :] -> out.
__global__ void prep_kernel(const float* __restrict__ x,
                            const float* __restrict__ W,
                            const float* __restrict__ bvec,
                            float* __restrict__ out) {
    int idx = blockIdx.x * blockDim.x + threadIdx.x;
    float dw = W[0] - W[1];
    float db = bvec[0] - bvec[1];
    if (idx < BB * LL * EE) {
        float v = x[idx];
        float z = fmaf(v, dw, db);
        g_S[idx] = __frcp_rn(1.0f + __expf(-z));   // sigmoid
    }
    if (idx < BB * (TT + 1) * EE) {
        int e = idx % EE;
        int t = (idx / EE) % (TT + 1);
        int b = idx / (EE * (TT + 1));
        out[((size_t)b * LOUT + t) * EE + e] = x[((size_t)b * LL + t) * EE + e];
    }
}

// Kernel 2: blocks[b,i,l,:] = fma(xi - xp, s0[b,l,:], xp)
// Grid: (83 i-tiles, 16 batches, 8 l-slices) = 10624 CTAs.
// 128 threads: lsub = tid/32 picks one of 4 l's per iteration, e4 = tid%32 is
// the float4 lane. All memory ops 128-bit, coalesced. Streaming stores.
__global__ void __launch_bounds__(128, 12)
blocks_kernel(const float* __restrict__ x, float* __restrict__ out) {
    const int b    = blockIdx.y;
    const int tile = blockIdx.x;
    const int zl   = blockIdx.z;
    const int tid  = threadIdx.x;
    const int lsub = tid >> 5;       // 0..3
    const int e4   = tid & 31;       // 0..31

    const float4* __restrict__ x4 = reinterpret_cast<const float4*>(x);
    const float4* __restrict__ S4 = reinterpret_cast<const float4*>(g_S);
    float4* __restrict__ o4       = reinterpret_cast<float4*>(out);

    const int ibase = tile * G;

    float4 dd[G], pp[G];
#pragma unroll
    for (int g = 0; g < G; g++) {
        int i = ibase + g;
        float4 a = __ldg(&x4[((size_t)b * LL + (TT + 1 + i)) * E4 + e4]);  // xi
        float4 p = __ldg(&x4[((size_t)b * LL + (i + 1)) * E4 + e4]);       // xp
        pp[g] = p;
        dd[g].x = a.x - p.x;
        dd[g].y = a.y - p.y;
        dd[g].z = a.z - p.z;
        dd[g].w = a.w - p.w;
    }

    const float4* __restrict__ Sb = S4 + (size_t)b * LL * E4;
    const size_t outrow0 = (size_t)b * LOUT + (TT + 1);
    const int lbeg = zl * LCH;

#pragma unroll
    for (int l0 = 0; l0 < LCH; l0 += 4) {
        const int l = lbeg + l0 + lsub;
        float4 s = __ldg(&Sb[(size_t)l * E4 + e4]);
#pragma unroll
        for (int g = 0; g < G; g++) {
            float4 o;
            o.x = fmaf(dd[g].x, s.x, pp[g].x);
            o.y = fmaf(dd[g].y, s.y, pp[g].y);
            o.z = fmaf(dd[g].z, s.z, pp[g].z);
            o.w = fmaf(dd[g].w, s.w, pp[g].w);
            __stcs(&o4[(outrow0 + (size_t)(ibase + g) * LL + l) * E4 + e4], o);
        }
    }
}

extern "C" void kernel_launch(void* const* d_in, const int* in_sizes, int n_in,
                              void* d_out, int out_size) {
    const float* x  = (const float*)d_in[0];
    const float* W  = (const float*)d_in[1];
    const float* bv = (const float*)d_in[2];
    float* out = (float*)d_out;

    int n1 = BB * LL * EE;
    prep_kernel<<<(n1 + 255) / 256, 256>>>(x, W, bv, out);

    dim3 grid(NI / G, BB, NZ);   // (83, 16, 8) = 10624 CTAs
    blocks_kernel<<<grid, 128>>>(x, out);
}

// round 4
// speedup vs baseline: 1.1889x; 1.0133x over previous
#include <cuda_runtime.h>

// Problem constants (from reference: B=16, L=192, E=128, T=25)
#define BB   16
#define LL   192
#define EE   128
#define TT   25
#define NI   (LL - TT - 1)          // 166 block rows per batch (even)
#define LOUT (TT + 1 + NI * LL)     // 31898 output rows per batch
#define E2   (EE / 2)               // 64 float2 per row
#define G    2                      // i-values per block
#define NZ   8                      // l-slices per (tile,b)
#define LCH  (LL / NZ)              // 24 l-values per slice

// Scratch: s0[b,l,e] = sigmoid(x*(W0-W1) + (b0-b1)). 1.5 MB (L2-resident).
__device__ float g_S[BB * LL * EE];

// Kernel 1: compute s0 table once; also copy the 26-row head x[:, :T+1, :] -> out.
__global__ void prep_kernel(const float* __restrict__ x,
                            const float* __restrict__ W,
                            const float* __restrict__ bvec,
                            float* __restrict__ out) {
    int idx = blockIdx.x * blockDim.x + threadIdx.x;
    float dw = W[0] - W[1];
    float db = bvec[0] - bvec[1];
    if (idx < BB * LL * EE) {
        float v = x[idx];
        float z = fmaf(v, dw, db);
        g_S[idx] = __frcp_rn(1.0f + __expf(-z));   // sigmoid
    }
    if (idx < BB * (TT + 1) * EE) {
        int e = idx % EE;
        int t = (idx / EE) % (TT + 1);
        int b = idx / (EE * (TT + 1));
        out[((size_t)b * LOUT + t) * EE + e] = x[((size_t)b * LL + t) * EE + e];
    }
}

// Kernel 2: blocks[b,i,l,:] = fma(xi - xp, s0[b,l,:], xp)
// Grid: (83 i-tiles, 16 batches, 8 l-slices) = 10624 CTAs, 256 threads.
// float2 granularity: e2 = tid%64 spans the 128-float row, lsub = tid/64
// picks one of 4 l's per iteration. ~30 regs/thread -> near-full occupancy.
__global__ void __launch_bounds__(256, 8)
blocks_kernel(const float* __restrict__ x, float* __restrict__ out) {
    const int b    = blockIdx.y;
    const int tile = blockIdx.x;
    const int zl   = blockIdx.z;
    const int tid  = threadIdx.x;
    const int lsub = tid >> 6;       // 0..3
    const int e2   = tid & 63;       // 0..63

    const float2* __restrict__ x2 = reinterpret_cast<const float2*>(x);
    const float2* __restrict__ S2 = reinterpret_cast<const float2*>(g_S);
    float2* __restrict__ o2       = reinterpret_cast<float2*>(out);

    const int ibase = tile * G;

    float2 dd[G], pp[G];
#pragma unroll
    for (int g = 0; g < G; g++) {
        int i = ibase + g;
        float2 a = __ldg(&x2[((size_t)b * LL + (TT + 1 + i)) * E2 + e2]);  // xi
        float2 p = __ldg(&x2[((size_t)b * LL + (i + 1)) * E2 + e2]);       // xp
        pp[g] = p;
        dd[g].x = a.x - p.x;
        dd[g].y = a.y - p.y;
    }

    const float2* __restrict__ Sb = S2 + (size_t)b * LL * E2;
    const size_t outrow0 = (size_t)b * LOUT + (TT + 1);
    const int lbeg = zl * LCH;

#pragma unroll
    for (int l0 = 0; l0 < LCH; l0 += 4) {
        const int l = lbeg + l0 + lsub;
        float2 s = __ldg(&Sb[(size_t)l * E2 + e2]);
#pragma unroll
        for (int g = 0; g < G; g++) {
            float2 o;
            o.x = fmaf(dd[g].x, s.x, pp[g].x);
            o.y = fmaf(dd[g].y, s.y, pp[g].y);
            __stcs(&o2[(outrow0 + (size_t)(ibase + g) * LL + l) * E2 + e2], o);
        }
    }
}

extern "C" void kernel_launch(void* const* d_in, const int* in_sizes, int n_in,
                              void* d_out, int out_size) {
    const float* x  = (const float*)d_in[0];
    const float* W  = (const float*)d_in[1];
    const float* bv = (const float*)d_in[2];
    float* out = (float*)d_out;

    int n1 = BB * LL * EE;
    prep_kernel<<<(n1 + 255) / 256, 256>>>(x, W, bv, out);

    dim3 grid(NI / G, BB, NZ);   // (83, 16, 8) = 10624 CTAs
    blocks_kernel<<<grid, 256>>>(x, out);
}